// round 10
// baseline (speedup 1.0000x reference)
#include <cuda_runtime.h>
#include <cstdint>

#define BATCH 16
#define HW    262144
#define NPIX  4194304

// ---------------- scratch (device globals; no runtime allocation) ----------
// q,k packed rows: per (b,h), 1024 floats = 32 groups x (16 hi | 16 lo), k-permuted
__device__ float g_qp[NPIX * 2], g_kp[NPIX * 2];
__device__ float g_vT[BATCH * 8 * HW];      // [B,C,W,H] (h k-permuted)
__device__ float g_attn[BATCH * HW];        // [B,H,H] (j k-permuted after softmax)

// ---------------- helpers ---------------------------------------------------
__device__ __forceinline__ float tf32r(float x) {
    uint32_t u; asm("cvt.rna.tf32.f32 %0, %1;" : "=r"(u) : "f"(x));
    return __uint_as_float(u);
}
__device__ __forceinline__ int kperm(int k) {
    return (k & ~15) | ((k & 3) << 2) | ((k >> 2) & 3);
}
#define CPA16(s, g)   asm volatile("cp.async.cg.shared.global [%0], [%1], 16;" :: "r"(s), "l"(g) : "memory")
#define CPA_COMMIT()  asm volatile("cp.async.commit_group;" ::: "memory")
#define CPA_WAIT(n)   asm volatile("cp.async.wait_group %0;" :: "n"(n) : "memory")

__device__ __forceinline__ uint32_t smem_u32(const void* p) {
    uint32_t a;
    asm("{ .reg .u64 t; cvta.to.shared.u64 t, %1; cvt.u32.u64 %0, t; }" : "=r"(a) : "l"(p));
    return a;
}
// chunk-level swizzle: row r (128B rows), 16B chunk ch (0..7).
// f depends only on r&7 -> rows differing by multiples of 8 share it.
__device__ __forceinline__ uint32_t swz128(int r, int ch) {
    const int f = ((r & 1) << 2) | ((r >> 1) & 3);
    return (uint32_t)(r * 128 + ((ch ^ f) << 4));
}
__device__ __forceinline__ uint4 lds128(uint32_t a) {
    uint4 v;
    asm volatile("ld.shared.v4.b32 {%0,%1,%2,%3}, [%4];"
                 : "=r"(v.x), "=r"(v.y), "=r"(v.z), "=r"(v.w) : "r"(a));
    return v;
}
#define MMA4(c, a0, a1, a2, a3, b0, b1) \
    asm volatile("mma.sync.aligned.m16n8k8.row.col.f32.tf32.tf32.f32 " \
                 "{%0,%1,%2,%3},{%4,%5,%6,%7},{%8,%9},{%0,%1,%2,%3};" \
                 : "+f"((c)[0]), "+f"((c)[1]), "+f"((c)[2]), "+f"((c)[3]) \
                 : "r"(a0), "r"(a1), "r"(a2), "r"(a3), "r"(b0), "r"(b1))

// ---------------------------------------------------------------------------
// Fused q/k/v 1x1 convs.  q,k written as packed hi/lo tf32 rows (1024 wide,
// k-permuted); v transposed to [B,C,W,H] (tf32, h k-permuted).
// ---------------------------------------------------------------------------
__global__ void __launch_bounds__(256)
qkv_kernel(const float* __restrict__ x,
           const float* __restrict__ Wq, const float* __restrict__ bq,
           const float* __restrict__ Wk, const float* __restrict__ bk,
           const float* __restrict__ Wv, const float* __restrict__ bv)
{
    __shared__ float sWq[8], sWk[8], sWv[64], sBv[8], sB2[2];
    __shared__ float sv[8][32][33];
    const int tid = threadIdx.x;
    if (tid < 8) { sWq[tid] = Wq[tid]; sWk[tid] = Wk[tid]; sBv[tid] = bv[tid]; }
    if (tid >= 8 && tid < 72) sWv[tid - 8] = Wv[tid - 8];
    if (tid == 72) sB2[0] = bq[0];
    if (tid == 73) sB2[1] = bk[0];
    __syncthreads();

    const int b = blockIdx.z, h0 = blockIdx.y * 32, w0 = blockIdx.x * 32;
    const int j = tid & 31, i0 = tid >> 5;

    for (int ii = 0; ii < 4; ii++) {
        const int i = i0 + ii * 8;
        const int h = h0 + i, w = w0 + j;
        const size_t pb = ((size_t)b * 8) * HW + (size_t)h * 512 + w;
        float xv[8];
#pragma unroll
        for (int c = 0; c < 8; c++) xv[c] = x[pb + (size_t)c * HW];

        float q = sB2[0], k = sB2[1];
#pragma unroll
        for (int c = 0; c < 8; c++) { q += xv[c] * sWq[c]; k += xv[c] * sWk[c]; }
        const int grp = w >> 4, pos = ((w & 3) << 2) | ((w >> 2) & 3);
        const size_t p = ((size_t)b * 512 + h) * 1024 + grp * 32 + pos;
        const float qh = tf32r(q), kh = tf32r(k);
        g_qp[p] = qh; g_qp[p + 16] = tf32r(q - qh);
        g_kp[p] = kh; g_kp[p + 16] = tf32r(k - kh);

#pragma unroll
        for (int o = 0; o < 8; o++) {
            float v = sBv[o];
#pragma unroll
            for (int c = 0; c < 8; c++) v += xv[c] * sWv[o * 8 + c];
            sv[o][i][j] = tf32r(v);
        }
    }
    __syncthreads();

    for (int ii = 0; ii < 4; ii++) {
        const int wl = i0 + ii * 8;
        const int hl = j;
#pragma unroll
        for (int c = 0; c < 8; c++) {
            g_vT[(((size_t)b * 8 + c) * 512 + (w0 + wl)) * 512 + kperm(h0 + hl)] = sv[c][hl][wl];
        }
    }
}

// ---------------------------------------------------------------------------
// GEMM kernels: C[m,n] = sum_k A[m,k]*B[n,k], per-z 512x512x512.
// 256 threads, 8 warps in 2(m) x 4(n): warp tile 64x32.  CTA 128x128.
// 3-stage cp.async, 32KB/stage -> 96KB -> 2 CTAs/SM (16 warps, 4/SMSP).
// LDS/MMA: gemm_out 16/64 = 0.25; gemm_logits 32/96 = 0.33.
// ---------------------------------------------------------------------------
__global__ void __launch_bounds__(256, 2)
gemm_logits(const float* __restrict__ Ab, const float* __restrict__ Bb,
            float* __restrict__ Cb)
{
    constexpr int ROWLEN = 1024;       // packed hi/lo rows
    constexpr int NCH    = 32;         // 16 logical k per chunk
    constexpr int STAGES = 3;
    constexpr uint32_t TA = 128 * 32 * 4;
    constexpr uint32_t SB = 2 * TA;

    extern __shared__ char smem[];
    const uint32_t s0 = smem_u32(smem);

    const int tid  = threadIdx.x;
    const int lane = tid & 31;
    const int wid  = tid >> 5;
    const int wm   = (wid & 1) * 64;
    const int wn   = (wid >> 1) * 32;
    const int gid  = lane >> 2;
    const int tig  = lane & 3;

    const int z = blockIdx.z;
    const size_t m0 = (size_t)blockIdx.y * 128;
    const size_t n0 = (size_t)blockIdx.x * 128;
    const float* A = Ab + (size_t)z * 512 * ROWLEN;
    const float* B = Bb + (size_t)z * 512 * ROWLEN;
    float* C = Cb + (size_t)z * HW;

    uint32_t bA[2], bB[2];    // sel 0 = hi chunks, sel 1 = lo chunks
#pragma unroll
    for (int s = 0; s < 2; s++) {
        bA[s] = swz128(wm + gid, s * 4 + tig);
        bB[s] = TA + swz128(wn + gid, s * 4 + tig);
    }

    const int seg  = tid & 7;
    const int row0 = tid >> 3;
    const uint32_t lsw0 = swz128(row0, seg);
    const float* Arow = A + (m0 + row0) * ROWLEN + seg * 4;
    const float* Brow = B + (n0 + row0) * ROWLEN + seg * 4;

    auto load_chunk = [&](int c, uint32_t base) {
        const uint32_t sb = base + lsw0;
        const int go = c * 32;
#pragma unroll
        for (int i = 0; i < 4; i++) {
            CPA16(sb + i * 4096,      Arow + go + i * 32 * ROWLEN);
            CPA16(sb + TA + i * 4096, Brow + go + i * 32 * ROWLEN);
        }
    };

    float acc[4][4][4] = {};

    uint32_t stW = s0, stR = s0;
#pragma unroll
    for (int c = 0; c < STAGES - 1; c++) {
        load_chunk(c, stW); CPA_COMMIT();
        stW += SB; if (stW == s0 + STAGES * SB) stW = s0;
    }

    for (int c = 0; c < NCH; c++) {
        CPA_WAIT(STAGES - 2);
        __syncthreads();
        if (c + STAGES - 1 < NCH) load_chunk(c + STAGES - 1, stW);
        CPA_COMMIT();
        stW += SB; if (stW == s0 + STAGES * SB) stW = s0;

        const uint32_t sA = stR;
        stR += SB; if (stR == s0 + STAGES * SB) stR = s0;

#pragma unroll
        for (int half = 0; half < 2; half++) {      // 32-row A halves
            const uint32_t aH = sA + bA[0] + half * 4096;
            const uint32_t aL = sA + bA[1] + half * 4096;
            uint4 ah[4], al[4];
#pragma unroll
            for (int i = 0; i < 4; i++) { ah[i] = lds128(aH + i * 1024); al[i] = lds128(aL + i * 1024); }
#pragma unroll
            for (int nt = 0; nt < 4; nt++) {
                const uint4 bh = lds128(sA + bB[0] + nt * 1024);
                const uint4 bl = lds128(sA + bB[1] + nt * 1024);
#pragma unroll
                for (int m2 = 0; m2 < 2; m2++) {
                    float* a0 = acc[half * 2 + m2][nt];
                    const uint4 &x = ah[2 * m2], &y = ah[2 * m2 + 1];
                    const uint4 &u = al[2 * m2], &v = al[2 * m2 + 1];
                    MMA4(a0, x.x, y.x, x.y, y.y, bh.x, bh.y);
                    MMA4(a0, u.x, v.x, u.y, v.y, bh.x, bh.y);
                    MMA4(a0, x.x, y.x, x.y, y.y, bl.x, bl.y);
                    MMA4(a0, x.z, y.z, x.w, y.w, bh.z, bh.w);
                    MMA4(a0, u.z, v.z, u.w, v.w, bh.z, bh.w);
                    MMA4(a0, x.z, y.z, x.w, y.w, bl.z, bl.w);
                }
            }
        }
    }

#pragma unroll
    for (int mt = 0; mt < 4; mt++) {
        const size_t r0 = m0 + wm + mt * 16 + gid;
#pragma unroll
        for (int nt = 0; nt < 4; nt++) {
            const size_t cc = n0 + wn + nt * 8 + tig * 2;
            *(float2*)(C + r0 * 512 + cc)       = make_float2(acc[mt][nt][0], acc[mt][nt][1]);
            *(float2*)(C + (r0 + 8) * 512 + cc) = make_float2(acc[mt][nt][2], acc[mt][nt][3]);
        }
    }
}

__global__ void __launch_bounds__(256, 2)
gemm_out(const float* __restrict__ Ab, const float* __restrict__ Bb,
         float* __restrict__ Cb)
{
    constexpr int STAGES = 3;
    constexpr uint32_t TA = 128 * 32 * 4;
    constexpr uint32_t SB = 2 * TA;

    extern __shared__ char smem[];
    const uint32_t s0 = smem_u32(smem);

    const int tid  = threadIdx.x;
    const int lane = tid & 31;
    const int wid  = tid >> 5;
    const int wm   = (wid & 1) * 64;
    const int wn   = (wid >> 1) * 32;
    const int gid  = lane >> 2;
    const int tig  = lane & 3;

    const int z = blockIdx.z;
    const size_t m0 = (size_t)blockIdx.y * 128;
    const size_t n0 = (size_t)blockIdx.x * 128;
    const float* A = Ab + (size_t)(z >> 3) * HW;   // attn shared across 8 channels
    const float* B = Bb + (size_t)z * HW;
    float* C = Cb + (size_t)z * HW;

    uint32_t bA[2], bB[2];
#pragma unroll
    for (int s = 0; s < 2; s++) {
        bA[s] = swz128(wm + gid, s * 4 + tig);
        bB[s] = TA + swz128(wn + gid, s * 4 + tig);
    }

    const int seg  = tid & 7;
    const int row0 = tid >> 3;
    const uint32_t lsw0 = swz128(row0, seg);
    const float* Arow = A + (m0 + row0) * 512 + seg * 4;
    const float* Brow = B + (n0 + row0) * 512 + seg * 4;

    auto load_chunk = [&](int c, uint32_t base) {
        const uint32_t sb = base + lsw0;
        const int go = c * 32;
#pragma unroll
        for (int i = 0; i < 4; i++) {
            CPA16(sb + i * 4096,      Arow + go + i * 32 * 512);
            CPA16(sb + TA + i * 4096, Brow + go + i * 32 * 512);
        }
    };

    float acc[4][4][4] = {};

    uint32_t stW = s0, stR = s0;
#pragma unroll
    for (int c = 0; c < STAGES - 1; c++) {
        load_chunk(c, stW); CPA_COMMIT();
        stW += SB; if (stW == s0 + STAGES * SB) stW = s0;
    }

    for (int c = 0; c < 16; c++) {
        CPA_WAIT(STAGES - 2);
        __syncthreads();
        if (c + STAGES - 1 < 16) load_chunk(c + STAGES - 1, stW);
        CPA_COMMIT();
        stW += SB; if (stW == s0 + STAGES * SB) stW = s0;

        const uint32_t sA = stR;
        stR += SB; if (stR == s0 + STAGES * SB) stR = s0;

#pragma unroll
        for (int g = 0; g < 2; g++) {              // two 16-k halves of chunk
            const uint32_t aB  = sA + bA[g];
            const uint32_t bBs = sA + bB[g];
            uint4 a[8];
#pragma unroll
            for (int i = 0; i < 8; i++) a[i] = lds128(aB + i * 1024);
#pragma unroll
            for (int nt = 0; nt < 4; nt++) {
                const uint4 bv = lds128(bBs + nt * 1024);
#pragma unroll
                for (int mt = 0; mt < 4; mt++)
                    MMA4(acc[mt][nt], a[2*mt].x, a[2*mt+1].x, a[2*mt].y, a[2*mt+1].y, bv.x, bv.y);
#pragma unroll
                for (int mt = 0; mt < 4; mt++)
                    MMA4(acc[mt][nt], a[2*mt].z, a[2*mt+1].z, a[2*mt].w, a[2*mt+1].w, bv.z, bv.w);
            }
        }
    }

#pragma unroll
    for (int mt = 0; mt < 4; mt++) {
        const size_t r0 = m0 + wm + mt * 16 + gid;
#pragma unroll
        for (int nt = 0; nt < 4; nt++) {
            const size_t cc = n0 + wn + nt * 8 + tig * 2;
            *(float2*)(C + r0 * 512 + cc)       = make_float2(acc[mt][nt][0], acc[mt][nt][1]);
            *(float2*)(C + (r0 + 8) * 512 + cc) = make_float2(acc[mt][nt][2], acc[mt][nt][3]);
        }
    }
}

// ---------------------------------------------------------------------------
// Row softmax over g_attn; reads natural order, writes k-permuted + tf32.
// ---------------------------------------------------------------------------
__global__ void softmax_kernel()
{
    const int row = blockIdx.x;
    const int tid = threadIdx.x;
    float* rp = g_attn + (size_t)row * 512;

    float4 v = *(float4*)(rp + tid * 4);
    float m = fmaxf(fmaxf(v.x, v.y), fmaxf(v.z, v.w));
#pragma unroll
    for (int o = 16; o > 0; o >>= 1) m = fmaxf(m, __shfl_xor_sync(0xFFFFFFFFu, m, o));

    __shared__ float sred[4];
    const int wid = tid >> 5, lane = tid & 31;
    if (lane == 0) sred[wid] = m;
    __syncthreads();
    m = fmaxf(fmaxf(sred[0], sred[1]), fmaxf(sred[2], sred[3]));
    __syncthreads();

    v.x = __expf(v.x - m); v.y = __expf(v.y - m);
    v.z = __expf(v.z - m); v.w = __expf(v.w - m);
    float s = v.x + v.y + v.z + v.w;
#pragma unroll
    for (int o = 16; o > 0; o >>= 1) s += __shfl_xor_sync(0xFFFFFFFFu, s, o);
    if (lane == 0) sred[wid] = s;
    __syncthreads();
    s = sred[0] + sred[1] + sred[2] + sred[3];

    const float inv = 1.0f / s;
    const int G = tid >> 2, u = tid & 3;
    float* gp = rp + G * 16 + u;
    __syncthreads();
    gp[0]  = tf32r(v.x * inv);
    gp[4]  = tf32r(v.y * inv);
    gp[8]  = tf32r(v.z * inv);
    gp[12] = tf32r(v.w * inv);
}

// ---------------------------------------------------------------------------
extern "C" void kernel_launch(void* const* d_in, const int* in_sizes, int n_in,
                              void* d_out, int out_size)
{
    const float* x  = (const float*)d_in[0];
    const float* Wq = (const float*)d_in[1];
    const float* bq = (const float*)d_in[2];
    const float* Wk = (const float*)d_in[3];
    const float* bk = (const float*)d_in[4];
    const float* Wv = (const float*)d_in[5];
    const float* bv = (const float*)d_in[6];
    float* out = (float*)d_out;

    float *pqp, *pkp, *pvT, *pattn;
    cudaGetSymbolAddress((void**)&pqp,  g_qp);
    cudaGetSymbolAddress((void**)&pkp,  g_kp);
    cudaGetSymbolAddress((void**)&pvT,  g_vT);
    cudaGetSymbolAddress((void**)&pattn, g_attn);

    const int SMEM_G = 3 * 2 * 16384;   // 96 KB
    cudaFuncSetAttribute(gemm_logits, cudaFuncAttributeMaxDynamicSharedMemorySize, SMEM_G);
    cudaFuncSetAttribute(gemm_out,    cudaFuncAttributeMaxDynamicSharedMemorySize, SMEM_G);

    // 1) q,k packed hi/lo (permuted), vT (permuted)
    qkv_kernel<<<dim3(16, 16, BATCH), 256>>>(x, Wq, bq, Wk, bk, Wv, bv);

    // 2) logits = q k^T per batch (3xTF32, packed)
    gemm_logits<<<dim3(4, 4, BATCH), 256, SMEM_G>>>(pqp, pkp, pattn);

    // 3) softmax rows (+ tf32 rounding + j-permutation)
    softmax_kernel<<<BATCH * 512, 128>>>();

    // 4) out = attn @ vT per (b,c), single tf32, warp tile 64x32
    gemm_out<<<dim3(4, 4, BATCH * 8), 256, SMEM_G>>>(pattn, pvT, out);
}

// round 11
// speedup vs baseline: 1.0324x; 1.0324x over previous
#include <cuda_runtime.h>
#include <cstdint>

#define BATCH 16
#define HW    262144
#define NPIX  4194304

// ---------------- scratch (device globals; no runtime allocation) ----------
// q,k packed rows: per (b,h), 1024 floats = 32 groups x (16 hi | 16 lo), k-permuted
__device__ float g_qp[NPIX * 2], g_kp[NPIX * 2];
__device__ float g_vT[BATCH * 8 * HW];      // [B,C,W,H] (h k-permuted)
__device__ float g_attn[BATCH * HW];        // [B,H,H] (j k-permuted after softmax)

// ---------------- helpers ---------------------------------------------------
__device__ __forceinline__ float tf32r(float x) {
    uint32_t u; asm("cvt.rna.tf32.f32 %0, %1;" : "=r"(u) : "f"(x));
    return __uint_as_float(u);
}
__device__ __forceinline__ int kperm(int k) {
    return (k & ~15) | ((k & 3) << 2) | ((k >> 2) & 3);
}
// cp.async with compile-time immediate offsets on both addresses
template <int SO, int GO>
__device__ __forceinline__ void cpa(uint32_t s, const float* g) {
    asm volatile("cp.async.cg.shared.global [%0+%1], [%2+%3], 16;"
                 :: "r"(s), "n"(SO), "l"(g), "n"(GO) : "memory");
}
#define CPA_COMMIT()  asm volatile("cp.async.commit_group;" ::: "memory")
#define CPA_WAIT0()   asm volatile("cp.async.wait_group 0;" ::: "memory")

__device__ __forceinline__ uint32_t smem_u32(const void* p) {
    uint32_t a;
    asm("{ .reg .u64 t; cvta.to.shared.u64 t, %1; cvt.u32.u64 %0, t; }" : "=r"(a) : "l"(p));
    return a;
}
// chunk-level swizzle: row r (128B rows), 16B chunk ch (0..7).
// f depends only on r&7 -> rows differing by multiples of 8 share it.
__device__ __forceinline__ uint32_t swz128(int r, int ch) {
    const int f = ((r & 1) << 2) | ((r >> 1) & 3);
    return (uint32_t)(r * 128 + ((ch ^ f) << 4));
}
__device__ __forceinline__ uint4 lds128(uint32_t a) {
    uint4 v;
    asm volatile("ld.shared.v4.b32 {%0,%1,%2,%3}, [%4];"
                 : "=r"(v.x), "=r"(v.y), "=r"(v.z), "=r"(v.w) : "r"(a));
    return v;
}
#define MMA4(c, a0, a1, a2, a3, b0, b1) \
    asm volatile("mma.sync.aligned.m16n8k8.row.col.f32.tf32.tf32.f32 " \
                 "{%0,%1,%2,%3},{%4,%5,%6,%7},{%8,%9},{%0,%1,%2,%3};" \
                 : "+f"((c)[0]), "+f"((c)[1]), "+f"((c)[2]), "+f"((c)[3]) \
                 : "r"(a0), "r"(a1), "r"(a2), "r"(a3), "r"(b0), "r"(b1))

// ---------------------------------------------------------------------------
// Fused q/k/v 1x1 convs.  q,k written as packed hi/lo tf32 rows (1024 wide,
// k-permuted); v transposed to [B,C,W,H] (tf32, h k-permuted).
// ---------------------------------------------------------------------------
__global__ void __launch_bounds__(256)
qkv_kernel(const float* __restrict__ x,
           const float* __restrict__ Wq, const float* __restrict__ bq,
           const float* __restrict__ Wk, const float* __restrict__ bk,
           const float* __restrict__ Wv, const float* __restrict__ bv)
{
    __shared__ float sWq[8], sWk[8], sWv[64], sBv[8], sB2[2];
    __shared__ float sv[8][32][33];
    const int tid = threadIdx.x;
    if (tid < 8) { sWq[tid] = Wq[tid]; sWk[tid] = Wk[tid]; sBv[tid] = bv[tid]; }
    if (tid >= 8 && tid < 72) sWv[tid - 8] = Wv[tid - 8];
    if (tid == 72) sB2[0] = bq[0];
    if (tid == 73) sB2[1] = bk[0];
    __syncthreads();

    const int b = blockIdx.z, h0 = blockIdx.y * 32, w0 = blockIdx.x * 32;
    const int j = tid & 31, i0 = tid >> 5;

    for (int ii = 0; ii < 4; ii++) {
        const int i = i0 + ii * 8;
        const int h = h0 + i, w = w0 + j;
        const size_t pb = ((size_t)b * 8) * HW + (size_t)h * 512 + w;
        float xv[8];
#pragma unroll
        for (int c = 0; c < 8; c++) xv[c] = x[pb + (size_t)c * HW];

        float q = sB2[0], k = sB2[1];
#pragma unroll
        for (int c = 0; c < 8; c++) { q += xv[c] * sWq[c]; k += xv[c] * sWk[c]; }
        const int grp = w >> 4, pos = ((w & 3) << 2) | ((w >> 2) & 3);
        const size_t p = ((size_t)b * 512 + h) * 1024 + grp * 32 + pos;
        const float qh = tf32r(q), kh = tf32r(k);
        g_qp[p] = qh; g_qp[p + 16] = tf32r(q - qh);
        g_kp[p] = kh; g_kp[p + 16] = tf32r(k - kh);

#pragma unroll
        for (int o = 0; o < 8; o++) {
            float v = sBv[o];
#pragma unroll
            for (int c = 0; c < 8; c++) v += xv[c] * sWv[o * 8 + c];
            sv[o][i][j] = tf32r(v);
        }
    }
    __syncthreads();

    for (int ii = 0; ii < 4; ii++) {
        const int wl = i0 + ii * 8;
        const int hl = j;
#pragma unroll
        for (int c = 0; c < 8; c++) {
            g_vT[(((size_t)b * 8 + c) * 512 + (w0 + wl)) * 512 + kperm(h0 + hl)] = sv[c][hl][wl];
        }
    }
}

// ---------------------------------------------------------------------------
// GEMM1 (logits, 3xTF32).  256 threads, 8 warps 4(m)x2(n), warp tile 32x64.
// Packed hi/lo rows 1024 wide, 32 chunks of 16 logical k.
// 2-stage double buffer, 64KB smem -> 2 CTAs/SM.  All SMEM addrs immediate.
// ---------------------------------------------------------------------------
__global__ void __launch_bounds__(256, 2)
gemm_logits(const float* __restrict__ Ab, const float* __restrict__ Bb,
            float* __restrict__ Cb)
{
    constexpr uint32_t TA = 16384, SB = 32768;

    extern __shared__ char smem[];
    const uint32_t s0 = smem_u32(smem);

    const int tid  = threadIdx.x;
    const int lane = tid & 31;
    const int wid  = tid >> 5;
    const int wm   = (wid & 3) * 32;
    const int wn   = (wid >> 2) * 64;
    const int gid  = lane >> 2;
    const int tig  = lane & 3;

    const int z = blockIdx.z;
    const size_t m0 = (size_t)blockIdx.y * 128;
    const size_t n0 = (size_t)blockIdx.x * 128;
    const float* A = Ab + (size_t)z * 512 * 1024;
    const float* B = Bb + (size_t)z * 512 * 1024;
    float* C = Cb + (size_t)z * HW;

    // fragment base registers (everything else is an immediate)
    const uint32_t Ah = s0 + swz128(wm + gid, tig);       // hi chunks (0..3)
    const uint32_t Al = s0 + swz128(wm + gid, 4 + tig);   // lo chunks (4..7)
    const uint32_t Bh = s0 + TA + swz128(wn + gid, tig);
    const uint32_t Bl = s0 + TA + swz128(wn + gid, 4 + tig);

    const int seg  = tid & 7;
    const int row0 = tid >> 3;
    const uint32_t lw = s0 + swz128(row0, seg);
    const float* Ap = A + (m0 + row0) * 1024 + seg * 4;
    const float* Bp = B + (n0 + row0) * 1024 + seg * 4;

#define GLOADL(SOFF) do { \
    cpa<(SOFF)+0,      0>(lw, Ap); cpa<(SOFF)+4096,  131072>(lw, Ap); \
    cpa<(SOFF)+8192,   262144>(lw, Ap); cpa<(SOFF)+12288, 393216>(lw, Ap); \
    cpa<(SOFF)+16384,  0>(lw, Bp); cpa<(SOFF)+20480, 131072>(lw, Bp); \
    cpa<(SOFF)+24576,  262144>(lw, Bp); cpa<(SOFF)+28672, 393216>(lw, Bp); \
    Ap += 32; Bp += 32; } while (0)

    float acc[2][8][4] = {};

    auto compute = [&](const uint32_t SC) {
        const uint4 h0 = lds128(Ah + SC),        h1 = lds128(Ah + SC + 1024);
        const uint4 h2 = lds128(Ah + SC + 2048), h3 = lds128(Ah + SC + 3072);
        const uint4 l0 = lds128(Al + SC),        l1 = lds128(Al + SC + 1024);
        const uint4 l2 = lds128(Al + SC + 2048), l3 = lds128(Al + SC + 3072);
#pragma unroll
        for (int nt = 0; nt < 8; nt++) {
            const uint4 bh = lds128(Bh + SC + nt * 1024);
            const uint4 bl = lds128(Bl + SC + nt * 1024);
            MMA4(acc[0][nt], h0.x, h1.x, h0.y, h1.y, bh.x, bh.y);
            MMA4(acc[0][nt], l0.x, l1.x, l0.y, l1.y, bh.x, bh.y);
            MMA4(acc[0][nt], h0.x, h1.x, h0.y, h1.y, bl.x, bl.y);
            MMA4(acc[0][nt], h0.z, h1.z, h0.w, h1.w, bh.z, bh.w);
            MMA4(acc[0][nt], l0.z, l1.z, l0.w, l1.w, bh.z, bh.w);
            MMA4(acc[0][nt], h0.z, h1.z, h0.w, h1.w, bl.z, bl.w);
            MMA4(acc[1][nt], h2.x, h3.x, h2.y, h3.y, bh.x, bh.y);
            MMA4(acc[1][nt], l2.x, l3.x, l2.y, l3.y, bh.x, bh.y);
            MMA4(acc[1][nt], h2.x, h3.x, h2.y, h3.y, bl.x, bl.y);
            MMA4(acc[1][nt], h2.z, h3.z, h2.w, h3.w, bh.z, bh.w);
            MMA4(acc[1][nt], l2.z, l3.z, l2.w, l3.w, bh.z, bh.w);
            MMA4(acc[1][nt], h2.z, h3.z, h2.w, h3.w, bl.z, bl.w);
        }
    };

    GLOADL(0); CPA_COMMIT();
    for (int c = 0; c < 32; c += 2) {
        CPA_WAIT0(); __syncthreads();
        if (c + 1 < 32) GLOADL(SB);
        CPA_COMMIT();
        compute(0);
        CPA_WAIT0(); __syncthreads();
        if (c + 2 < 32) GLOADL(0);
        CPA_COMMIT();
        compute(SB);
    }
#undef GLOADL

#pragma unroll
    for (int mt = 0; mt < 2; mt++) {
        const size_t r0 = m0 + wm + mt * 16 + gid;
#pragma unroll
        for (int nt = 0; nt < 8; nt++) {
            const size_t cc = n0 + wn + nt * 8 + tig * 2;
            *(float2*)(C + r0 * 512 + cc)       = make_float2(acc[mt][nt][0], acc[mt][nt][1]);
            *(float2*)(C + (r0 + 8) * 512 + cc) = make_float2(acc[mt][nt][2], acc[mt][nt][3]);
        }
    }
}

// ---------------------------------------------------------------------------
// GEMM2 (out = attn @ vT), single tf32.  Same shape: warp tile 32x64,
// rows 512 wide, 16 chunks of 32 k, 2-stage double buffer.
// ---------------------------------------------------------------------------
__global__ void __launch_bounds__(256, 2)
gemm_out(const float* __restrict__ Ab, const float* __restrict__ Bb,
         float* __restrict__ Cb)
{
    constexpr uint32_t TA = 16384, SB = 32768;

    extern __shared__ char smem[];
    const uint32_t s0 = smem_u32(smem);

    const int tid  = threadIdx.x;
    const int lane = tid & 31;
    const int wid  = tid >> 5;
    const int wm   = (wid & 3) * 32;
    const int wn   = (wid >> 2) * 64;
    const int gid  = lane >> 2;
    const int tig  = lane & 3;

    const int z = blockIdx.z;
    const size_t m0 = (size_t)blockIdx.y * 128;
    const size_t n0 = (size_t)blockIdx.x * 128;
    const float* A = Ab + (size_t)(z >> 3) * HW;   // attn shared across 8 channels
    const float* B = Bb + (size_t)z * HW;
    float* C = Cb + (size_t)z * HW;

    const uint32_t A0 = s0 + swz128(wm + gid, tig);
    const uint32_t A1 = s0 + swz128(wm + gid, 4 + tig);
    const uint32_t B0 = s0 + TA + swz128(wn + gid, tig);
    const uint32_t B1 = s0 + TA + swz128(wn + gid, 4 + tig);

    const int seg  = tid & 7;
    const int row0 = tid >> 3;
    const uint32_t lw = s0 + swz128(row0, seg);
    const float* Ap = A + (m0 + row0) * 512 + seg * 4;
    const float* Bp = B + (n0 + row0) * 512 + seg * 4;

#define GLOAD(SOFF) do { \
    cpa<(SOFF)+0,      0>(lw, Ap); cpa<(SOFF)+4096,  65536>(lw, Ap); \
    cpa<(SOFF)+8192,   131072>(lw, Ap); cpa<(SOFF)+12288, 196608>(lw, Ap); \
    cpa<(SOFF)+16384,  0>(lw, Bp); cpa<(SOFF)+20480, 65536>(lw, Bp); \
    cpa<(SOFF)+24576,  131072>(lw, Bp); cpa<(SOFF)+28672, 196608>(lw, Bp); \
    Ap += 32; Bp += 32; } while (0)

    float acc[2][8][4] = {};

    auto compute = [&](const uint32_t SC) {
#pragma unroll
        for (int g = 0; g < 2; g++) {
            const uint32_t aB = (g ? A1 : A0) + SC;
            const uint32_t bB = (g ? B1 : B0) + SC;
            const uint4 a0 = lds128(aB),        a1 = lds128(aB + 1024);
            const uint4 a2 = lds128(aB + 2048), a3 = lds128(aB + 3072);
#pragma unroll
            for (int nt = 0; nt < 8; nt++) {
                const uint4 bv = lds128(bB + nt * 1024);
                MMA4(acc[0][nt], a0.x, a1.x, a0.y, a1.y, bv.x, bv.y);
                MMA4(acc[1][nt], a2.x, a3.x, a2.y, a3.y, bv.x, bv.y);
                MMA4(acc[0][nt], a0.z, a1.z, a0.w, a1.w, bv.z, bv.w);
                MMA4(acc[1][nt], a2.z, a3.z, a2.w, a3.w, bv.z, bv.w);
            }
        }
    };

    GLOAD(0); CPA_COMMIT();
    for (int c = 0; c < 16; c += 2) {
        CPA_WAIT0(); __syncthreads();
        if (c + 1 < 16) GLOAD(SB);
        CPA_COMMIT();
        compute(0);
        CPA_WAIT0(); __syncthreads();
        if (c + 2 < 16) GLOAD(0);
        CPA_COMMIT();
        compute(SB);
    }
#undef GLOAD

#pragma unroll
    for (int mt = 0; mt < 2; mt++) {
        const size_t r0 = m0 + wm + mt * 16 + gid;
#pragma unroll
        for (int nt = 0; nt < 8; nt++) {
            const size_t cc = n0 + wn + nt * 8 + tig * 2;
            *(float2*)(C + r0 * 512 + cc)       = make_float2(acc[mt][nt][0], acc[mt][nt][1]);
            *(float2*)(C + (r0 + 8) * 512 + cc) = make_float2(acc[mt][nt][2], acc[mt][nt][3]);
        }
    }
}

// ---------------------------------------------------------------------------
// Row softmax over g_attn; reads natural order, writes k-permuted + tf32.
// ---------------------------------------------------------------------------
__global__ void softmax_kernel()
{
    const int row = blockIdx.x;
    const int tid = threadIdx.x;
    float* rp = g_attn + (size_t)row * 512;

    float4 v = *(float4*)(rp + tid * 4);
    float m = fmaxf(fmaxf(v.x, v.y), fmaxf(v.z, v.w));
#pragma unroll
    for (int o = 16; o > 0; o >>= 1) m = fmaxf(m, __shfl_xor_sync(0xFFFFFFFFu, m, o));

    __shared__ float sred[4];
    const int wid = tid >> 5, lane = tid & 31;
    if (lane == 0) sred[wid] = m;
    __syncthreads();
    m = fmaxf(fmaxf(sred[0], sred[1]), fmaxf(sred[2], sred[3]));
    __syncthreads();

    v.x = __expf(v.x - m); v.y = __expf(v.y - m);
    v.z = __expf(v.z - m); v.w = __expf(v.w - m);
    float s = v.x + v.y + v.z + v.w;
#pragma unroll
    for (int o = 16; o > 0; o >>= 1) s += __shfl_xor_sync(0xFFFFFFFFu, s, o);
    if (lane == 0) sred[wid] = s;
    __syncthreads();
    s = sred[0] + sred[1] + sred[2] + sred[3];

    const float inv = 1.0f / s;
    const int G = tid >> 2, u = tid & 3;
    float* gp = rp + G * 16 + u;
    __syncthreads();
    gp[0]  = tf32r(v.x * inv);
    gp[4]  = tf32r(v.y * inv);
    gp[8]  = tf32r(v.z * inv);
    gp[12] = tf32r(v.w * inv);
}

// ---------------------------------------------------------------------------
extern "C" void kernel_launch(void* const* d_in, const int* in_sizes, int n_in,
                              void* d_out, int out_size)
{
    const float* x  = (const float*)d_in[0];
    const float* Wq = (const float*)d_in[1];
    const float* bq = (const float*)d_in[2];
    const float* Wk = (const float*)d_in[3];
    const float* bk = (const float*)d_in[4];
    const float* Wv = (const float*)d_in[5];
    const float* bv = (const float*)d_in[6];
    float* out = (float*)d_out;

    float *pqp, *pkp, *pvT, *pattn;
    cudaGetSymbolAddress((void**)&pqp,  g_qp);
    cudaGetSymbolAddress((void**)&pkp,  g_kp);
    cudaGetSymbolAddress((void**)&pvT,  g_vT);
    cudaGetSymbolAddress((void**)&pattn, g_attn);

    const int SMEM_G = 2 * 32768;   // 64 KB (2-stage double buffer)
    cudaFuncSetAttribute(gemm_logits, cudaFuncAttributeMaxDynamicSharedMemorySize, SMEM_G);
    cudaFuncSetAttribute(gemm_out,    cudaFuncAttributeMaxDynamicSharedMemorySize, SMEM_G);

    // 1) q,k packed hi/lo (permuted), vT (permuted)
    qkv_kernel<<<dim3(16, 16, BATCH), 256>>>(x, Wq, bq, Wk, bk, Wv, bv);

    // 2) logits = q k^T per batch (3xTF32, packed)
    gemm_logits<<<dim3(4, 4, BATCH), 256, SMEM_G>>>(pqp, pkp, pattn);

    // 3) softmax rows (+ tf32 rounding + j-permutation)
    softmax_kernel<<<BATCH * 512, 128>>>();

    // 4) out = attn @ vT per (b,c), single tf32
    gemm_out<<<dim3(4, 4, BATCH * 8), 256, SMEM_G>>>(pattn, pvT, out);
}

// round 12
// speedup vs baseline: 1.6355x; 1.5841x over previous
#include <cuda_runtime.h>
#include <cuda_fp16.h>
#include <cstdint>

#define BATCH 16
#define HW    262144

// ---------------- scratch (device globals; no runtime allocation) ----------
// q,k packed rows: per (b,h), 1024 fp16 = 16 groups x (32 hi | 32 lo), k-permuted
__device__ __half g_qp[(size_t)BATCH * 512 * 1024];
__device__ __half g_kp[(size_t)BATCH * 512 * 1024];
__device__ __half g_vT[(size_t)BATCH * 8 * HW];     // [B,C,W,H] h 64-group-permuted
__device__ float  g_attn[(size_t)BATCH * HW];       // fp32 logits [B,H,H]
__device__ __half g_at16[(size_t)BATCH * HW];       // fp16 attn, j 64-group-permuted

// ---------------- helpers ---------------------------------------------------
// 16-k fragment permutation pieces
__device__ __forceinline__ int fp_t(int kk) { return (kk & 7) >> 1; }          // thread-in-group
__device__ __forceinline__ int fp_j(int kk) { return ((kk >> 3) << 1) | (kk & 1); }
// position within a 32-k packed group (gemm1 q/k): [t*8 + s*4 + j]
__device__ __forceinline__ int pos32(int k32) {
    const int s = k32 >> 4, kk = k32 & 15;
    return fp_t(kk) * 8 + s * 4 + fp_j(kk);
}
// position within a 64-k group (gemm2 attn/vT): [(s>>1)*32 + t*8 + (s&1)*4 + j]
__device__ __forceinline__ int pos64(int k64) {
    const int s = k64 >> 4, kk = k64 & 15;
    return ((s & 2) << 4) + fp_t(kk) * 8 + ((s & 1) << 2) + fp_j(kk);
}
template <int SO, int GO>
__device__ __forceinline__ void cpa(uint32_t s, const __half* g) {
    asm volatile("cp.async.cg.shared.global [%0+%1], [%2+%3], 16;"
                 :: "r"(s), "n"(SO), "l"(g), "n"(GO) : "memory");
}
#define CPA_COMMIT()  asm volatile("cp.async.commit_group;" ::: "memory")
#define CPA_WAIT0()   asm volatile("cp.async.wait_group 0;" ::: "memory")

__device__ __forceinline__ uint32_t smem_u32(const void* p) {
    uint32_t a;
    asm("{ .reg .u64 t; cvta.to.shared.u64 t, %1; cvt.u32.u64 %0, t; }" : "=r"(a) : "l"(p));
    return a;
}
// chunk-level swizzle: row r (128B rows), 16B chunk ch (0..7)
__device__ __forceinline__ uint32_t swz128(int r, int ch) {
    const int f = ((r & 1) << 2) | ((r >> 1) & 3);
    return (uint32_t)(r * 128 + ((ch ^ f) << 4));
}
__device__ __forceinline__ uint4 lds128(uint32_t a) {
    uint4 v;
    asm volatile("ld.shared.v4.b32 {%0,%1,%2,%3}, [%4];"
                 : "=r"(v.x), "=r"(v.y), "=r"(v.z), "=r"(v.w) : "r"(a));
    return v;
}
// fp16 MMA m16n8k16, fp32 accumulate
#define MMAH(c, a0, a1, a2, a3, b0, b1) \
    asm volatile("mma.sync.aligned.m16n8k16.row.col.f32.f16.f16.f32 " \
                 "{%0,%1,%2,%3},{%4,%5,%6,%7},{%8,%9},{%0,%1,%2,%3};" \
                 : "+f"((c)[0]), "+f"((c)[1]), "+f"((c)[2]), "+f"((c)[3]) \
                 : "r"(a0), "r"(a1), "r"(a2), "r"(a3), "r"(b0), "r"(b1))

// ---------------------------------------------------------------------------
// Fused q/k/v 1x1 convs -> fp16 operands in GEMM-ready permuted layouts.
// ---------------------------------------------------------------------------
__global__ void __launch_bounds__(256)
qkv_kernel(const float* __restrict__ x,
           const float* __restrict__ Wq, const float* __restrict__ bq,
           const float* __restrict__ Wk, const float* __restrict__ bk,
           const float* __restrict__ Wv, const float* __restrict__ bv)
{
    __shared__ float sWq[8], sWk[8], sWv[64], sBv[8], sB2[2];
    __shared__ __half sv[8][32][33];
    const int tid = threadIdx.x;
    if (tid < 8) { sWq[tid] = Wq[tid]; sWk[tid] = Wk[tid]; sBv[tid] = bv[tid]; }
    if (tid >= 8 && tid < 72) sWv[tid - 8] = Wv[tid - 8];
    if (tid == 72) sB2[0] = bq[0];
    if (tid == 73) sB2[1] = bk[0];
    __syncthreads();

    const int b = blockIdx.z, h0 = blockIdx.y * 32, w0 = blockIdx.x * 32;
    const int j = tid & 31, i0 = tid >> 5;

    for (int ii = 0; ii < 4; ii++) {
        const int i = i0 + ii * 8;
        const int h = h0 + i, w = w0 + j;
        const size_t pb = ((size_t)b * 8) * HW + (size_t)h * 512 + w;
        float xv[8];
#pragma unroll
        for (int c = 0; c < 8; c++) xv[c] = x[pb + (size_t)c * HW];

        float q = sB2[0], k = sB2[1];
#pragma unroll
        for (int c = 0; c < 8; c++) { q += xv[c] * sWq[c]; k += xv[c] * sWk[c]; }
        // packed hi/lo row: group g = w>>5 occupies [g*64, g*64+64): 32 hi | 32 lo
        const int g = w >> 5;
        const size_t base = ((size_t)b * 512 + h) * 1024 + g * 64 + pos32(w & 31);
        const __half qh = __float2half_rn(q);
        const __half kh = __float2half_rn(k);
        g_qp[base] = qh; g_qp[base + 32] = __float2half_rn(q - __half2float(qh));
        g_kp[base] = kh; g_kp[base + 32] = __float2half_rn(k - __half2float(kh));

#pragma unroll
        for (int o = 0; o < 8; o++) {
            float v = sBv[o];
#pragma unroll
            for (int c = 0; c < 8; c++) v += xv[c] * sWv[o * 8 + c];
            sv[o][i][j] = __float2half_rn(v);
        }
    }
    __syncthreads();

    // vT[b,c,w, perm64(h)]
    for (int ii = 0; ii < 4; ii++) {
        const int wl = i0 + ii * 8;
        const int hl = j;
        const int h = h0 + hl;
        const int pp = (h & ~63) + pos64(h & 63);
#pragma unroll
        for (int c = 0; c < 8; c++) {
            g_vT[(((size_t)b * 8 + c) * 512 + (w0 + wl)) * 512 + pp] = sv[c][hl][wl];
        }
    }
}

// ---------------------------------------------------------------------------
// GEMM1 (logits, fp16 hi/lo 3-pass).  256 thr, 8 warps 4(m)x2(n), tile 32x64.
// Rows 1024 fp16 (16 groups x [32hi|32lo]); chunk = one group = 128B/row.
// 2-stage double buffer, 64KB -> 2 CTAs/SM.  All SMEM addrs immediate.
// ---------------------------------------------------------------------------
__global__ void __launch_bounds__(256, 2)
gemm_logits(const __half* __restrict__ Ab, const __half* __restrict__ Bb,
            float* __restrict__ Cb)
{
    constexpr uint32_t TA = 16384, SB = 32768;

    extern __shared__ char smem[];
    const uint32_t s0 = smem_u32(smem);

    const int tid  = threadIdx.x;
    const int lane = tid & 31;
    const int wid  = tid >> 5;
    const int wm   = (wid & 3) * 32;
    const int wn   = (wid >> 2) * 64;
    const int gid  = lane >> 2;
    const int tig  = lane & 3;

    const int z = blockIdx.z;
    const size_t m0 = (size_t)blockIdx.y * 128;
    const size_t n0 = (size_t)blockIdx.x * 128;
    const __half* A = Ab + (size_t)z * 512 * 1024;
    const __half* B = Bb + (size_t)z * 512 * 1024;
    float* C = Cb + (size_t)z * HW;

    // fragment bases: hi at ch=tig, lo at ch=4+tig
    const uint32_t Ah = s0 + swz128(wm + gid, tig);
    const uint32_t Al = s0 + swz128(wm + gid, 4 + tig);
    const uint32_t Bh = s0 + TA + swz128(wn + gid, tig);
    const uint32_t Bl = s0 + TA + swz128(wn + gid, 4 + tig);

    const int seg  = tid & 7;
    const int row0 = tid >> 3;
    const uint32_t lw = s0 + swz128(row0, seg);
    const __half* Ap = A + (m0 + row0) * 1024 + seg * 8;
    const __half* Bp = B + (n0 + row0) * 1024 + seg * 8;

#define GLOADL(SOFF) do { \
    cpa<(SOFF)+0,          0>(lw, Ap); cpa<(SOFF)+4096,   65536>(lw, Ap); \
    cpa<(SOFF)+8192,  131072>(lw, Ap); cpa<(SOFF)+12288, 196608>(lw, Ap); \
    cpa<(SOFF)+16384,      0>(lw, Bp); cpa<(SOFF)+20480,  65536>(lw, Bp); \
    cpa<(SOFF)+24576, 131072>(lw, Bp); cpa<(SOFF)+28672, 196608>(lw, Bp); \
    Ap += 64; Bp += 64; } while (0)

    float acc[2][8][4] = {};

    auto compute = [&](const uint32_t SC) {
        const uint4 h0 = lds128(Ah + SC),        h1 = lds128(Ah + SC + 1024);
        const uint4 h2 = lds128(Ah + SC + 2048), h3 = lds128(Ah + SC + 3072);
        const uint4 l0 = lds128(Al + SC),        l1 = lds128(Al + SC + 1024);
        const uint4 l2 = lds128(Al + SC + 2048), l3 = lds128(Al + SC + 3072);
#pragma unroll
        for (int nt = 0; nt < 8; nt++) {
            const uint4 bh = lds128(Bh + SC + nt * 1024);
            const uint4 bl = lds128(Bl + SC + nt * 1024);
            // m-tile 0 (rows gid, gid+8): steps 0 (x,y) and 1 (z,w)
            MMAH(acc[0][nt], h0.x, h1.x, h0.y, h1.y, bh.x, bh.y);
            MMAH(acc[0][nt], l0.x, l1.x, l0.y, l1.y, bh.x, bh.y);
            MMAH(acc[0][nt], h0.x, h1.x, h0.y, h1.y, bl.x, bl.y);
            MMAH(acc[0][nt], h0.z, h1.z, h0.w, h1.w, bh.z, bh.w);
            MMAH(acc[0][nt], l0.z, l1.z, l0.w, l1.w, bh.z, bh.w);
            MMAH(acc[0][nt], h0.z, h1.z, h0.w, h1.w, bl.z, bl.w);
            // m-tile 1 (rows gid+16, gid+24)
            MMAH(acc[1][nt], h2.x, h3.x, h2.y, h3.y, bh.x, bh.y);
            MMAH(acc[1][nt], l2.x, l3.x, l2.y, l3.y, bh.x, bh.y);
            MMAH(acc[1][nt], h2.x, h3.x, h2.y, h3.y, bl.x, bl.y);
            MMAH(acc[1][nt], h2.z, h3.z, h2.w, h3.w, bh.z, bh.w);
            MMAH(acc[1][nt], l2.z, l3.z, l2.w, l3.w, bh.z, bh.w);
            MMAH(acc[1][nt], h2.z, h3.z, h2.w, h3.w, bl.z, bl.w);
        }
    };

    GLOADL(0); CPA_COMMIT();
    for (int c = 0; c < 16; c += 2) {
        CPA_WAIT0(); __syncthreads();
        if (c + 1 < 16) GLOADL(SB);
        CPA_COMMIT();
        compute(0);
        CPA_WAIT0(); __syncthreads();
        if (c + 2 < 16) GLOADL(0);
        CPA_COMMIT();
        compute(SB);
    }
#undef GLOADL

#pragma unroll
    for (int mt = 0; mt < 2; mt++) {
        const size_t r0 = m0 + wm + mt * 16 + gid;
#pragma unroll
        for (int nt = 0; nt < 8; nt++) {
            const size_t cc = n0 + wn + nt * 8 + tig * 2;
            *(float2*)(C + r0 * 512 + cc)       = make_float2(acc[mt][nt][0], acc[mt][nt][1]);
            *(float2*)(C + (r0 + 8) * 512 + cc) = make_float2(acc[mt][nt][2], acc[mt][nt][3]);
        }
    }
}

// ---------------------------------------------------------------------------
// GEMM2 (out = attn @ vT), fp16 single pass.  Rows 512 fp16 in 64-groups;
// chunk = 64 k = 128B/row, 8 chunks.  Same warp layout + double buffer.
// ---------------------------------------------------------------------------
__global__ void __launch_bounds__(256, 2)
gemm_out(const __half* __restrict__ Ab, const __half* __restrict__ Bb,
         float* __restrict__ Cb)
{
    constexpr uint32_t TA = 16384, SB = 32768;

    extern __shared__ char smem[];
    const uint32_t s0 = smem_u32(smem);

    const int tid  = threadIdx.x;
    const int lane = tid & 31;
    const int wid  = tid >> 5;
    const int wm   = (wid & 3) * 32;
    const int wn   = (wid >> 2) * 64;
    const int gid  = lane >> 2;
    const int tig  = lane & 3;

    const int z = blockIdx.z;
    const size_t m0 = (size_t)blockIdx.y * 128;
    const size_t n0 = (size_t)blockIdx.x * 128;
    const __half* A = Ab + (size_t)(z >> 3) * HW;   // attn shared across 8 channels
    const __half* B = Bb + (size_t)z * HW;
    float* C = Cb + (size_t)z * HW;

    // steps 0,1 at ch=tig; steps 2,3 at ch=4+tig
    const uint32_t A0 = s0 + swz128(wm + gid, tig);
    const uint32_t A1 = s0 + swz128(wm + gid, 4 + tig);
    const uint32_t B0 = s0 + TA + swz128(wn + gid, tig);
    const uint32_t B1 = s0 + TA + swz128(wn + gid, 4 + tig);

    const int seg  = tid & 7;
    const int row0 = tid >> 3;
    const uint32_t lw = s0 + swz128(row0, seg);
    const __half* Ap = A + (m0 + row0) * 512 + seg * 8;
    const __half* Bp = B + (n0 + row0) * 512 + seg * 8;

#define GLOAD(SOFF) do { \
    cpa<(SOFF)+0,          0>(lw, Ap); cpa<(SOFF)+4096,   32768>(lw, Ap); \
    cpa<(SOFF)+8192,   65536>(lw, Ap); cpa<(SOFF)+12288,  98304>(lw, Ap); \
    cpa<(SOFF)+16384,      0>(lw, Bp); cpa<(SOFF)+20480,  32768>(lw, Bp); \
    cpa<(SOFF)+24576,  65536>(lw, Bp); cpa<(SOFF)+28672,  98304>(lw, Bp); \
    Ap += 64; Bp += 64; } while (0)

    float acc[2][8][4] = {};

    auto compute = [&](const uint32_t SC) {
#pragma unroll
        for (int g = 0; g < 2; g++) {          // steps (0,1) then (2,3)
            const uint32_t aB = (g ? A1 : A0) + SC;
            const uint32_t bB = (g ? B1 : B0) + SC;
            const uint4 a0 = lds128(aB),        a1 = lds128(aB + 1024);
            const uint4 a2 = lds128(aB + 2048), a3 = lds128(aB + 3072);
#pragma unroll
            for (int nt = 0; nt < 8; nt++) {
                const uint4 bv = lds128(bB + nt * 1024);
                MMAH(acc[0][nt], a0.x, a1.x, a0.y, a1.y, bv.x, bv.y);
                MMAH(acc[1][nt], a2.x, a3.x, a2.y, a3.y, bv.x, bv.y);
                MMAH(acc[0][nt], a0.z, a1.z, a0.w, a1.w, bv.z, bv.w);
                MMAH(acc[1][nt], a2.z, a3.z, a2.w, a3.w, bv.z, bv.w);
            }
        }
    };

    GLOAD(0); CPA_COMMIT();
    for (int c = 0; c < 8; c += 2) {
        CPA_WAIT0(); __syncthreads();
        if (c + 1 < 8) GLOAD(SB);
        CPA_COMMIT();
        compute(0);
        CPA_WAIT0(); __syncthreads();
        if (c + 2 < 8) GLOAD(0);
        CPA_COMMIT();
        compute(SB);
    }
#undef GLOAD

#pragma unroll
    for (int mt = 0; mt < 2; mt++) {
        const size_t r0 = m0 + wm + mt * 16 + gid;
#pragma unroll
        for (int nt = 0; nt < 8; nt++) {
            const size_t cc = n0 + wn + nt * 8 + tig * 2;
            *(float2*)(C + r0 * 512 + cc)       = make_float2(acc[mt][nt][0], acc[mt][nt][1]);
            *(float2*)(C + (r0 + 8) * 512 + cc) = make_float2(acc[mt][nt][2], acc[mt][nt][3]);
        }
    }
}

// ---------------------------------------------------------------------------
// Row softmax: reads fp32 logits, writes fp16 attn with 64-group permutation.
// ---------------------------------------------------------------------------
__global__ void softmax_kernel()
{
    const int row = blockIdx.x;
    const int tid = threadIdx.x;
    const float* rp = g_attn + (size_t)row * 512;
    __half* op = g_at16 + (size_t)row * 512;

    float4 v = *(const float4*)(rp + tid * 4);
    float m = fmaxf(fmaxf(v.x, v.y), fmaxf(v.z, v.w));
#pragma unroll
    for (int o = 16; o > 0; o >>= 1) m = fmaxf(m, __shfl_xor_sync(0xFFFFFFFFu, m, o));

    __shared__ float sred[4];
    const int wid = tid >> 5, lane = tid & 31;
    if (lane == 0) sred[wid] = m;
    __syncthreads();
    m = fmaxf(fmaxf(sred[0], sred[1]), fmaxf(sred[2], sred[3]));
    __syncthreads();

    v.x = __expf(v.x - m); v.y = __expf(v.y - m);
    v.z = __expf(v.z - m); v.w = __expf(v.w - m);
    float s = v.x + v.y + v.z + v.w;
#pragma unroll
    for (int o = 16; o > 0; o >>= 1) s += __shfl_xor_sync(0xFFFFFFFFu, s, o);
    if (lane == 0) sred[wid] = s;
    __syncthreads();
    s = sred[0] + sred[1] + sred[2] + sred[3];

    const float inv = 1.0f / s;
    const int c0 = tid * 4;
    const float r4[4] = { v.x * inv, v.y * inv, v.z * inv, v.w * inv };
#pragma unroll
    for (int i = 0; i < 4; i++) {
        const int k = c0 + i;
        op[(k & ~63) + pos64(k & 63)] = __float2half_rn(r4[i]);
    }
}

// ---------------------------------------------------------------------------
extern "C" void kernel_launch(void* const* d_in, const int* in_sizes, int n_in,
                              void* d_out, int out_size)
{
    const float* x  = (const float*)d_in[0];
    const float* Wq = (const float*)d_in[1];
    const float* bq = (const float*)d_in[2];
    const float* Wk = (const float*)d_in[3];
    const float* bk = (const float*)d_in[4];
    const float* Wv = (const float*)d_in[5];
    const float* bv = (const float*)d_in[6];
    float* out = (float*)d_out;

    __half *pqp, *pkp, *pvT, *pat16;
    float* pattn;
    cudaGetSymbolAddress((void**)&pqp,   g_qp);
    cudaGetSymbolAddress((void**)&pkp,   g_kp);
    cudaGetSymbolAddress((void**)&pvT,   g_vT);
    cudaGetSymbolAddress((void**)&pattn, g_attn);
    cudaGetSymbolAddress((void**)&pat16, g_at16);

    const int SMEM_G = 2 * 32768;   // 64 KB double buffer
    cudaFuncSetAttribute(gemm_logits, cudaFuncAttributeMaxDynamicSharedMemorySize, SMEM_G);
    cudaFuncSetAttribute(gemm_out,    cudaFuncAttributeMaxDynamicSharedMemorySize, SMEM_G);

    // 1) q,k packed fp16 hi/lo (permuted), vT fp16 (permuted)
    qkv_kernel<<<dim3(16, 16, BATCH), 256>>>(x, Wq, bq, Wk, bk, Wv, bv);

    // 2) logits = q k^T per batch (fp16 3-pass hi/lo)
    gemm_logits<<<dim3(4, 4, BATCH), 256, SMEM_G>>>(pqp, pkp, pattn);

    // 3) softmax rows -> fp16 permuted attn
    softmax_kernel<<<BATCH * 512, 128>>>();

    // 4) out = attn @ vT per (b,c), fp16 single pass
    gemm_out<<<dim3(4, 4, BATCH * 8), 256, SMEM_G>>>(pat16, pvT, out);
}

// round 13
// speedup vs baseline: 1.6839x; 1.0296x over previous
#include <cuda_runtime.h>
#include <cuda_fp16.h>
#include <cstdint>

#define BATCH 16
#define HW    262144

// ---------------- scratch (device globals; no runtime allocation) ----------
// q,k packed rows: per (b,h), 1024 fp16 = 16 groups x (32 hi | 32 lo), k-permuted
__device__ __half g_qp[(size_t)BATCH * 512 * 1024];
__device__ __half g_kp[(size_t)BATCH * 512 * 1024];
__device__ __half g_vT[(size_t)BATCH * 8 * HW];     // [B,C,W,H] h 64-group-permuted
__device__ float  g_attn[(size_t)BATCH * HW];       // fp32 logits [B,H,H]
__device__ __half g_at16[(size_t)BATCH * HW];       // fp16 attn, j 64-group-permuted

// ---------------- helpers ---------------------------------------------------
__device__ __forceinline__ int fp_t(int kk) { return (kk & 7) >> 1; }
__device__ __forceinline__ int fp_j(int kk) { return ((kk >> 3) << 1) | (kk & 1); }
__device__ __forceinline__ int pos32(int k32) {
    const int s = k32 >> 4, kk = k32 & 15;
    return fp_t(kk) * 8 + s * 4 + fp_j(kk);
}
__device__ __forceinline__ int pos64(int k64) {
    const int s = k64 >> 4, kk = k64 & 15;
    return ((s & 2) << 4) + fp_t(kk) * 8 + ((s & 1) << 2) + fp_j(kk);
}
template <int SO, int GO>
__device__ __forceinline__ void cpa(uint32_t s, const __half* g) {
    asm volatile("cp.async.cg.shared.global [%0+%1], [%2+%3], 16;"
                 :: "r"(s), "n"(SO), "l"(g), "n"(GO) : "memory");
}
#define CPA_COMMIT()  asm volatile("cp.async.commit_group;" ::: "memory")
#define CPA_WAIT0()   asm volatile("cp.async.wait_group 0;" ::: "memory")

__device__ __forceinline__ uint32_t smem_u32(const void* p) {
    uint32_t a;
    asm("{ .reg .u64 t; cvta.to.shared.u64 t, %1; cvt.u32.u64 %0, t; }" : "=r"(a) : "l"(p));
    return a;
}
__device__ __forceinline__ uint32_t swz128(int r, int ch) {
    const int f = ((r & 1) << 2) | ((r >> 1) & 3);
    return (uint32_t)(r * 128 + ((ch ^ f) << 4));
}
__device__ __forceinline__ uint4 lds128(uint32_t a) {
    uint4 v;
    asm volatile("ld.shared.v4.b32 {%0,%1,%2,%3}, [%4];"
                 : "=r"(v.x), "=r"(v.y), "=r"(v.z), "=r"(v.w) : "r"(a));
    return v;
}
#define MMAH(c, a0, a1, a2, a3, b0, b1) \
    asm volatile("mma.sync.aligned.m16n8k16.row.col.f32.f16.f16.f32 " \
                 "{%0,%1,%2,%3},{%4,%5,%6,%7},{%8,%9},{%0,%1,%2,%3};" \
                 : "+f"((c)[0]), "+f"((c)[1]), "+f"((c)[2]), "+f"((c)[3]) \
                 : "r"(a0), "r"(a1), "r"(a2), "r"(a3), "r"(b0), "r"(b1))

// ---------------------------------------------------------------------------
// Fused q/k/v 1x1 convs -> fp16 operands in GEMM-ready permuted layouts.
// ---------------------------------------------------------------------------
__global__ void __launch_bounds__(256)
qkv_kernel(const float* __restrict__ x,
           const float* __restrict__ Wq, const float* __restrict__ bq,
           const float* __restrict__ Wk, const float* __restrict__ bk,
           const float* __restrict__ Wv, const float* __restrict__ bv)
{
    __shared__ float sWq[8], sWk[8], sWv[64], sBv[8], sB2[2];
    __shared__ __half sv[8][32][33];
    const int tid = threadIdx.x;
    if (tid < 8) { sWq[tid] = Wq[tid]; sWk[tid] = Wk[tid]; sBv[tid] = bv[tid]; }
    if (tid >= 8 && tid < 72) sWv[tid - 8] = Wv[tid - 8];
    if (tid == 72) sB2[0] = bq[0];
    if (tid == 73) sB2[1] = bk[0];
    __syncthreads();

    const int b = blockIdx.z, h0 = blockIdx.y * 32, w0 = blockIdx.x * 32;
    const int j = tid & 31, i0 = tid >> 5;

    for (int ii = 0; ii < 4; ii++) {
        const int i = i0 + ii * 8;
        const int h = h0 + i, w = w0 + j;
        const size_t pb = ((size_t)b * 8) * HW + (size_t)h * 512 + w;
        float xv[8];
#pragma unroll
        for (int c = 0; c < 8; c++) xv[c] = x[pb + (size_t)c * HW];

        float q = sB2[0], k = sB2[1];
#pragma unroll
        for (int c = 0; c < 8; c++) { q += xv[c] * sWq[c]; k += xv[c] * sWk[c]; }
        const int g = w >> 5;
        const size_t base = ((size_t)b * 512 + h) * 1024 + g * 64 + pos32(w & 31);
        const __half qh = __float2half_rn(q);
        const __half kh = __float2half_rn(k);
        g_qp[base] = qh; g_qp[base + 32] = __float2half_rn(q - __half2float(qh));
        g_kp[base] = kh; g_kp[base + 32] = __float2half_rn(k - __half2float(kh));

#pragma unroll
        for (int o = 0; o < 8; o++) {
            float v = sBv[o];
#pragma unroll
            for (int c = 0; c < 8; c++) v += xv[c] * sWv[o * 8 + c];
            sv[o][i][j] = __float2half_rn(v);
        }
    }
    __syncthreads();

    for (int ii = 0; ii < 4; ii++) {
        const int wl = i0 + ii * 8;
        const int hl = j;
        const int h = h0 + hl;
        const int pp = (h & ~63) + pos64(h & 63);
#pragma unroll
        for (int c = 0; c < 8; c++) {
            g_vT[(((size_t)b * 8 + c) * 512 + (w0 + wl)) * 512 + pp] = sv[c][hl][wl];
        }
    }
}

// ---------------------------------------------------------------------------
// GEMM1 (logits, fp16 hi/lo 3-pass).  256 thr, 8 warps 4(m)x2(n), tile 32x64.
// MMA phases swept with nt pairs innermost -> same-acc separation = 4 MMAs.
// ---------------------------------------------------------------------------
__global__ void __launch_bounds__(256, 2)
gemm_logits(const __half* __restrict__ Ab, const __half* __restrict__ Bb,
            float* __restrict__ Cb)
{
    constexpr uint32_t TA = 16384, SB = 32768;

    extern __shared__ char smem[];
    const uint32_t s0 = smem_u32(smem);

    const int tid  = threadIdx.x;
    const int lane = tid & 31;
    const int wid  = tid >> 5;
    const int wm   = (wid & 3) * 32;
    const int wn   = (wid >> 2) * 64;
    const int gid  = lane >> 2;
    const int tig  = lane & 3;

    const int z = blockIdx.z;
    const size_t m0 = (size_t)blockIdx.y * 128;
    const size_t n0 = (size_t)blockIdx.x * 128;
    const __half* A = Ab + (size_t)z * 512 * 1024;
    const __half* B = Bb + (size_t)z * 512 * 1024;
    float* C = Cb + (size_t)z * HW;

    const uint32_t Ah = s0 + swz128(wm + gid, tig);
    const uint32_t Al = s0 + swz128(wm + gid, 4 + tig);
    const uint32_t Bh = s0 + TA + swz128(wn + gid, tig);
    const uint32_t Bl = s0 + TA + swz128(wn + gid, 4 + tig);

    const int seg  = tid & 7;
    const int row0 = tid >> 3;
    const uint32_t lw = s0 + swz128(row0, seg);
    const __half* Ap = A + (m0 + row0) * 1024 + seg * 8;
    const __half* Bp = B + (n0 + row0) * 1024 + seg * 8;

#define GLOADL(SOFF) do { \
    cpa<(SOFF)+0,          0>(lw, Ap); cpa<(SOFF)+4096,   65536>(lw, Ap); \
    cpa<(SOFF)+8192,  131072>(lw, Ap); cpa<(SOFF)+12288, 196608>(lw, Ap); \
    cpa<(SOFF)+16384,      0>(lw, Bp); cpa<(SOFF)+20480,  65536>(lw, Bp); \
    cpa<(SOFF)+24576, 131072>(lw, Bp); cpa<(SOFF)+28672, 196608>(lw, Bp); \
    Ap += 64; Bp += 64; } while (0)

    float acc[2][8][4] = {};

    auto compute = [&](const uint32_t SC) {
        const uint4 h0 = lds128(Ah + SC),        h1 = lds128(Ah + SC + 1024);
        const uint4 h2 = lds128(Ah + SC + 2048), h3 = lds128(Ah + SC + 3072);
        const uint4 l0 = lds128(Al + SC),        l1 = lds128(Al + SC + 1024);
        const uint4 l2 = lds128(Al + SC + 2048), l3 = lds128(Al + SC + 3072);
#pragma unroll
        for (int q = 0; q < 4; q++) {           // nt pairs
            uint4 bh[2], bl[2];
#pragma unroll
            for (int i = 0; i < 2; i++) {
                bh[i] = lds128(Bh + SC + (q * 2 + i) * 1024);
                bl[i] = lds128(Bl + SC + (q * 2 + i) * 1024);
            }
            // step 0 (x,y) phases
#pragma unroll
            for (int i = 0; i < 2; i++) MMAH(acc[0][q*2+i], h0.x, h1.x, h0.y, h1.y, bh[i].x, bh[i].y);
#pragma unroll
            for (int i = 0; i < 2; i++) MMAH(acc[1][q*2+i], h2.x, h3.x, h2.y, h3.y, bh[i].x, bh[i].y);
#pragma unroll
            for (int i = 0; i < 2; i++) MMAH(acc[0][q*2+i], l0.x, l1.x, l0.y, l1.y, bh[i].x, bh[i].y);
#pragma unroll
            for (int i = 0; i < 2; i++) MMAH(acc[1][q*2+i], l2.x, l3.x, l2.y, l3.y, bh[i].x, bh[i].y);
#pragma unroll
            for (int i = 0; i < 2; i++) MMAH(acc[0][q*2+i], h0.x, h1.x, h0.y, h1.y, bl[i].x, bl[i].y);
#pragma unroll
            for (int i = 0; i < 2; i++) MMAH(acc[1][q*2+i], h2.x, h3.x, h2.y, h3.y, bl[i].x, bl[i].y);
            // step 1 (z,w) phases
#pragma unroll
            for (int i = 0; i < 2; i++) MMAH(acc[0][q*2+i], h0.z, h1.z, h0.w, h1.w, bh[i].z, bh[i].w);
#pragma unroll
            for (int i = 0; i < 2; i++) MMAH(acc[1][q*2+i], h2.z, h3.z, h2.w, h3.w, bh[i].z, bh[i].w);
#pragma unroll
            for (int i = 0; i < 2; i++) MMAH(acc[0][q*2+i], l0.z, l1.z, l0.w, l1.w, bh[i].z, bh[i].w);
#pragma unroll
            for (int i = 0; i < 2; i++) MMAH(acc[1][q*2+i], l2.z, l3.z, l2.w, l3.w, bh[i].z, bh[i].w);
#pragma unroll
            for (int i = 0; i < 2; i++) MMAH(acc[0][q*2+i], h0.z, h1.z, h0.w, h1.w, bl[i].z, bl[i].w);
#pragma unroll
            for (int i = 0; i < 2; i++) MMAH(acc[1][q*2+i], h2.z, h3.z, h2.w, h3.w, bl[i].z, bl[i].w);
        }
    };

    GLOADL(0); CPA_COMMIT();
    for (int c = 0; c < 16; c += 2) {
        CPA_WAIT0(); __syncthreads();
        if (c + 1 < 16) GLOADL(SB);
        CPA_COMMIT();
        compute(0);
        CPA_WAIT0(); __syncthreads();
        if (c + 2 < 16) GLOADL(0);
        CPA_COMMIT();
        compute(SB);
    }
#undef GLOADL

#pragma unroll
    for (int mt = 0; mt < 2; mt++) {
        const size_t r0 = m0 + wm + mt * 16 + gid;
#pragma unroll
        for (int nt = 0; nt < 8; nt++) {
            const size_t cc = n0 + wn + nt * 8 + tig * 2;
            *(float2*)(C + r0 * 512 + cc)       = make_float2(acc[mt][nt][0], acc[mt][nt][1]);
            *(float2*)(C + (r0 + 8) * 512 + cc) = make_float2(acc[mt][nt][2], acc[mt][nt][3]);
        }
    }
}

// ---------------------------------------------------------------------------
// GEMM2 (out = attn @ vT), fp16 single pass.  Phases swept with nt halves
// innermost -> same-acc separation = 8 MMAs.
// ---------------------------------------------------------------------------
__global__ void __launch_bounds__(256, 2)
gemm_out(const __half* __restrict__ Ab, const __half* __restrict__ Bb,
         float* __restrict__ Cb)
{
    constexpr uint32_t TA = 16384, SB = 32768;

    extern __shared__ char smem[];
    const uint32_t s0 = smem_u32(smem);

    const int tid  = threadIdx.x;
    const int lane = tid & 31;
    const int wid  = tid >> 5;
    const int wm   = (wid & 3) * 32;
    const int wn   = (wid >> 2) * 64;
    const int gid  = lane >> 2;
    const int tig  = lane & 3;

    const int z = blockIdx.z;
    const size_t m0 = (size_t)blockIdx.y * 128;
    const size_t n0 = (size_t)blockIdx.x * 128;
    const __half* A = Ab + (size_t)(z >> 3) * HW;
    const __half* B = Bb + (size_t)z * HW;
    float* C = Cb + (size_t)z * HW;

    const uint32_t A0 = s0 + swz128(wm + gid, tig);
    const uint32_t A1 = s0 + swz128(wm + gid, 4 + tig);
    const uint32_t B0 = s0 + TA + swz128(wn + gid, tig);
    const uint32_t B1 = s0 + TA + swz128(wn + gid, 4 + tig);

    const int seg  = tid & 7;
    const int row0 = tid >> 3;
    const uint32_t lw = s0 + swz128(row0, seg);
    const __half* Ap = A + (m0 + row0) * 512 + seg * 8;
    const __half* Bp = B + (n0 + row0) * 512 + seg * 8;

#define GLOAD(SOFF) do { \
    cpa<(SOFF)+0,          0>(lw, Ap); cpa<(SOFF)+4096,   32768>(lw, Ap); \
    cpa<(SOFF)+8192,   65536>(lw, Ap); cpa<(SOFF)+12288,  98304>(lw, Ap); \
    cpa<(SOFF)+16384,      0>(lw, Bp); cpa<(SOFF)+20480,  32768>(lw, Bp); \
    cpa<(SOFF)+24576,  65536>(lw, Bp); cpa<(SOFF)+28672,  98304>(lw, Bp); \
    Ap += 64; Bp += 64; } while (0)

    float acc[2][8][4] = {};

    auto compute = [&](const uint32_t SC) {
#pragma unroll
        for (int g = 0; g < 2; g++) {
            const uint32_t aB = (g ? A1 : A0) + SC;
            const uint32_t bB = (g ? B1 : B0) + SC;
            const uint4 a0 = lds128(aB),        a1 = lds128(aB + 1024);
            const uint4 a2 = lds128(aB + 2048), a3 = lds128(aB + 3072);
#pragma unroll
            for (int h = 0; h < 2; h++) {      // nt halves of 4
                uint4 bv[4];
#pragma unroll
                for (int i = 0; i < 4; i++) bv[i] = lds128(bB + (h * 4 + i) * 1024);
#pragma unroll
                for (int i = 0; i < 4; i++)
                    MMAH(acc[0][h*4+i], a0.x, a1.x, a0.y, a1.y, bv[i].x, bv[i].y);
#pragma unroll
                for (int i = 0; i < 4; i++)
                    MMAH(acc[1][h*4+i], a2.x, a3.x, a2.y, a3.y, bv[i].x, bv[i].y);
#pragma unroll
                for (int i = 0; i < 4; i++)
                    MMAH(acc[0][h*4+i], a0.z, a1.z, a0.w, a1.w, bv[i].z, bv[i].w);
#pragma unroll
                for (int i = 0; i < 4; i++)
                    MMAH(acc[1][h*4+i], a2.z, a3.z, a2.w, a3.w, bv[i].z, bv[i].w);
            }
        }
    };

    GLOAD(0); CPA_COMMIT();
    for (int c = 0; c < 8; c += 2) {
        CPA_WAIT0(); __syncthreads();
        if (c + 1 < 8) GLOAD(SB);
        CPA_COMMIT();
        compute(0);
        CPA_WAIT0(); __syncthreads();
        if (c + 2 < 8) GLOAD(0);
        CPA_COMMIT();
        compute(SB);
    }
#undef GLOAD

#pragma unroll
    for (int mt = 0; mt < 2; mt++) {
        const size_t r0 = m0 + wm + mt * 16 + gid;
#pragma unroll
        for (int nt = 0; nt < 8; nt++) {
            const size_t cc = n0 + wn + nt * 8 + tig * 2;
            *(float2*)(C + r0 * 512 + cc)       = make_float2(acc[mt][nt][0], acc[mt][nt][1]);
            *(float2*)(C + (r0 + 8) * 512 + cc) = make_float2(acc[mt][nt][2], acc[mt][nt][3]);
        }
    }
}

// ---------------------------------------------------------------------------
// Row softmax: reads fp32 logits, writes fp16 attn with 64-group permutation.
// ---------------------------------------------------------------------------
__global__ void softmax_kernel()
{
    const int row = blockIdx.x;
    const int tid = threadIdx.x;
    const float* rp = g_attn + (size_t)row * 512;
    __half* op = g_at16 + (size_t)row * 512;

    float4 v = *(const float4*)(rp + tid * 4);
    float m = fmaxf(fmaxf(v.x, v.y), fmaxf(v.z, v.w));
#pragma unroll
    for (int o = 16; o > 0; o >>= 1) m = fmaxf(m, __shfl_xor_sync(0xFFFFFFFFu, m, o));

    __shared__ float sred[4];
    const int wid = tid >> 5, lane = tid & 31;
    if (lane == 0) sred[wid] = m;
    __syncthreads();
    m = fmaxf(fmaxf(sred[0], sred[1]), fmaxf(sred[2], sred[3]));
    __syncthreads();

    v.x = __expf(v.x - m); v.y = __expf(v.y - m);
    v.z = __expf(v.z - m); v.w = __expf(v.w - m);
    float s = v.x + v.y + v.z + v.w;
#pragma unroll
    for (int o = 16; o > 0; o >>= 1) s += __shfl_xor_sync(0xFFFFFFFFu, s, o);
    if (lane == 0) sred[wid] = s;
    __syncthreads();
    s = sred[0] + sred[1] + sred[2] + sred[3];

    const float inv = 1.0f / s;
    const int c0 = tid * 4;
    const float r4[4] = { v.x * inv, v.y * inv, v.z * inv, v.w * inv };
#pragma unroll
    for (int i = 0; i < 4; i++) {
        const int k = c0 + i;
        op[(k & ~63) + pos64(k & 63)] = __float2half_rn(r4[i]);
    }
}

// ---------------------------------------------------------------------------
extern "C" void kernel_launch(void* const* d_in, const int* in_sizes, int n_in,
                              void* d_out, int out_size)
{
    const float* x  = (const float*)d_in[0];
    const float* Wq = (const float*)d_in[1];
    const float* bq = (const float*)d_in[2];
    const float* Wk = (const float*)d_in[3];
    const float* bk = (const float*)d_in[4];
    const float* Wv = (const float*)d_in[5];
    const float* bv = (const float*)d_in[6];
    float* out = (float*)d_out;

    __half *pqp, *pkp, *pvT, *pat16;
    float* pattn;
    cudaGetSymbolAddress((void**)&pqp,   g_qp);
    cudaGetSymbolAddress((void**)&pkp,   g_kp);
    cudaGetSymbolAddress((void**)&pvT,   g_vT);
    cudaGetSymbolAddress((void**)&pattn, g_attn);
    cudaGetSymbolAddress((void**)&pat16, g_at16);

    const int SMEM_G = 2 * 32768;   // 64 KB double buffer
    cudaFuncSetAttribute(gemm_logits, cudaFuncAttributeMaxDynamicSharedMemorySize, SMEM_G);
    cudaFuncSetAttribute(gemm_out,    cudaFuncAttributeMaxDynamicSharedMemorySize, SMEM_G);

    // 1) q,k packed fp16 hi/lo (permuted), vT fp16 (permuted)
    qkv_kernel<<<dim3(16, 16, BATCH), 256>>>(x, Wq, bq, Wk, bk, Wv, bv);

    // 2) logits = q k^T per batch (fp16 3-pass hi/lo)
    gemm_logits<<<dim3(4, 4, BATCH), 256, SMEM_G>>>(pqp, pkp, pattn);

    // 3) softmax rows -> fp16 permuted attn
    softmax_kernel<<<BATCH * 512, 128>>>();

    // 4) out = attn @ vT per (b,c), fp16 single pass
    gemm_out<<<dim3(4, 4, BATCH * 8), 256, SMEM_G>>>(pat16, pvT, out);
}